// round 11
// baseline (speedup 1.0000x reference)
#include <cuda_runtime.h>
#include <cuda_bf16.h>
#include <math_constants.h>

// VQ forward: z (B,256) f32, embed (512,256) f32.
// out = [ quantized (B*256) | codes (B, as float) | commit (1) ]  (float32)
//
// Numerics contract (validated R9, PASS):
//   dot:    single-accumulator fp32 fma chain, k ascending (per row,col)
//   z_sq/e_sq: XLA:GPU row-reduce (vec=2, 128 thr, shfl trees)
//   dist = (z_sq - (2.0f*dot)) + e_sq  (separately rounded)
//   argmin: strict <, ascending col, tie -> lower index
//   quantized = z + (q - z), separately rounded
//
// R10: f32x2 GEMM with zero inner-loop movs:
//   lanes = row pairs; a = LDS.128 from k-major Z tile (2 operands/load)
//   b = pre-duplicated E tile (Ed[k][n] = (e,e)) -> direct LDS.64
//   micro-tile 8 rows x 4 cols (strided cols), TM=128, TN=64.

#define D_DIM 256
#define K_CODES 512
#define TM 128
#define TN 64
#define TK 16
#define NTHREADS 256
#define B_MAX 262144

__device__ float g_esq[K_CODES];
__device__ float g_zsq[B_MAX];
__device__ float g_partials[8192];

__device__ __forceinline__ void fma2(unsigned long long& d,
                                     unsigned long long a,
                                     unsigned long long b) {
    asm("fma.rn.f32x2 %0, %1, %2, %0;" : "+l"(d) : "l"(a), "l"(b));
}
__device__ __forceinline__ float2 upk2(unsigned long long v) {
    float2 f;
    asm("mov.b64 {%0, %1}, %2;" : "=f"(f.x), "=f"(f.y) : "l"(v));
    return f;
}

// XLA:GPU row-reduce replica for sum(x*x) over a 256-float row.
// 128 threads per row (2 rows per 256-thread block).
// dest==0 -> g_esq, dest==1 -> g_zsq
__global__ void k_rowsq_xla(const float* __restrict__ x, int rows, int dest) {
    __shared__ float w[8];
    const unsigned full = 0xffffffffu;
    int grp = threadIdx.x >> 7;
    int t = threadIdx.x & 127;
    long row = (long)blockIdx.x * 2 + grp;

    float s = 0.f;
    if (row < rows) {
        const float2 v = *(const float2*)(x + row * D_DIM + 2 * t);
        s = __fadd_rn(__fmul_rn(v.x, v.x), __fmul_rn(v.y, v.y));
    }
    s = __fadd_rn(s, __shfl_down_sync(full, s, 16));
    s = __fadd_rn(s, __shfl_down_sync(full, s, 8));
    s = __fadd_rn(s, __shfl_down_sync(full, s, 4));
    s = __fadd_rn(s, __shfl_down_sync(full, s, 2));
    s = __fadd_rn(s, __shfl_down_sync(full, s, 1));
    if ((threadIdx.x & 31) == 0) w[threadIdx.x >> 5] = s;
    __syncthreads();
    if ((t >> 5) == 0) {
        int lane = t & 31;
        float v = (lane < 4) ? w[grp * 4 + lane] : 0.f;
        v = __fadd_rn(v, __shfl_down_sync(full, v, 16));
        v = __fadd_rn(v, __shfl_down_sync(full, v, 8));
        v = __fadd_rn(v, __shfl_down_sync(full, v, 4));
        v = __fadd_rn(v, __shfl_down_sync(full, v, 2));
        v = __fadd_rn(v, __shfl_down_sync(full, v, 1));
        if (lane == 0 && row < rows) {
            if (dest == 0) g_esq[row] = v;
            else           g_zsq[row] = v;
        }
    }
}

__global__ __launch_bounds__(NTHREADS)
void k_main(const float* __restrict__ z, const float* __restrict__ embed,
            float* __restrict__ out, int B, int write_codes) {
    __shared__ __align__(16) float  Zs[TK][TM];     // 8KB  k-major Z tile
    __shared__ __align__(16) float2 Ed[TK][TN];     // 8KB  duplicated E tile
    __shared__ float sMin[TM][16];                  // 8KB
    __shared__ int   sIdx[TM][16];                  // 8KB
    __shared__ int   sCode[TM];
    __shared__ float sPart[NTHREADS];
    __shared__ float sZsq[TM];

    const int tid = threadIdx.x;
    const int tx = tid & 15;            // owns cols tx + 16c, c=0..3
    const int ty = tid >> 4;            // owns rows ty*8 .. ty*8+7
    const long rowBase = (long)blockIdx.x * TM;

    if (tid < TM) sZsq[tid] = g_zsq[rowBase + tid];

    float rmin[8];
    int   ridx[8];
#pragma unroll
    for (int r = 0; r < 8; r++) { rmin[r] = CUDART_INF_F; ridx[r] = 0; }

    const int mStage = tid & 63;        // staging coords
    const int kqStage = tid >> 6;       // 0..3

    for (int ct = 0; ct < K_CODES / TN; ++ct) {
        unsigned long long acc[4][4];   // [rowpair][col]
#pragma unroll
        for (int rp = 0; rp < 4; rp++)
#pragma unroll
            for (int c = 0; c < 4; c++) acc[rp][c] = 0ull;

        for (int kt = 0; kt < D_DIM / TK; ++kt) {
            __syncthreads();
            // ---- stage Z tile (transposed, conflict-free stores) ----
#pragma unroll
            for (int h = 0; h < 2; h++) {
                int m = h * 64 + mStage;
                float4 v = *(const float4*)(z + (rowBase + m) * D_DIM +
                                            kt * TK + kqStage * 4);
                Zs[kqStage * 4 + 0][m] = v.x;
                Zs[kqStage * 4 + 1][m] = v.y;
                Zs[kqStage * 4 + 2][m] = v.z;
                Zs[kqStage * 4 + 3][m] = v.w;
            }
            // ---- stage E tile, pre-duplicated ----
            {
                int n = mStage;
                float4 v = *(const float4*)(embed + (long)(ct * TN + n) * D_DIM +
                                            kt * TK + kqStage * 4);
                Ed[kqStage * 4 + 0][n] = make_float2(v.x, v.x);
                Ed[kqStage * 4 + 1][n] = make_float2(v.y, v.y);
                Ed[kqStage * 4 + 2][n] = make_float2(v.z, v.z);
                Ed[kqStage * 4 + 3][n] = make_float2(v.w, v.w);
            }
            __syncthreads();

            // ---- 16 k-steps: 2x LDS.128 (a) + 4x LDS.64 (b) + 16 FFMA2 ----
#pragma unroll
            for (int k = 0; k < TK; k++) {
                const unsigned long long* ap =
                    (const unsigned long long*)&Zs[k][ty * 8];
                unsigned long long a0 = ap[0];
                unsigned long long a1 = ap[1];
                unsigned long long a2 = ap[2];
                unsigned long long a3 = ap[3];
                const unsigned long long* bp =
                    (const unsigned long long*)&Ed[k][tx];
                unsigned long long b0 = bp[0];
                unsigned long long b1 = bp[16];
                unsigned long long b2 = bp[32];
                unsigned long long b3 = bp[48];
                fma2(acc[0][0], a0, b0); fma2(acc[0][1], a0, b1);
                fma2(acc[0][2], a0, b2); fma2(acc[0][3], a0, b3);
                fma2(acc[1][0], a1, b0); fma2(acc[1][1], a1, b1);
                fma2(acc[1][2], a1, b2); fma2(acc[1][3], a1, b3);
                fma2(acc[2][0], a2, b0); fma2(acc[2][1], a2, b1);
                fma2(acc[2][2], a2, b2); fma2(acc[2][3], a2, b3);
                fma2(acc[3][0], a3, b0); fma2(acc[3][1], a3, b1);
                fma2(acc[3][2], a3, b2); fma2(acc[3][3], a3, b3);
            }
        }

        // ---- dist + running argmin (cols ascending per thread) ----
#pragma unroll
        for (int c = 0; c < 4; c++) {
            int col = ct * TN + c * 16 + tx;
            float eq = g_esq[col];
#pragma unroll
            for (int rp = 0; rp < 4; rp++) {
                float2 d = upk2(acc[rp][c]);
                int r0 = 2 * rp, r1 = 2 * rp + 1;
                float zs0 = sZsq[ty * 8 + r0];
                float zs1 = sZsq[ty * 8 + r1];
                float s0 = __fadd_rn(__fsub_rn(zs0, __fmul_rn(2.0f, d.x)), eq);
                float s1 = __fadd_rn(__fsub_rn(zs1, __fmul_rn(2.0f, d.y)), eq);
                if (s0 < rmin[r0]) { rmin[r0] = s0; ridx[r0] = col; }
                if (s1 < rmin[r1]) { rmin[r1] = s1; ridx[r1] = col; }
            }
        }
    }

    // ---- cross-thread argmin reduce (lower index wins ties) ----
    __syncthreads();
#pragma unroll
    for (int r = 0; r < 8; r++) {
        sMin[ty * 8 + r][tx] = rmin[r];
        sIdx[ty * 8 + r][tx] = ridx[r];
    }
    __syncthreads();
    if (tid < TM) {
        float m = sMin[tid][0];
        int ix = sIdx[tid][0];
#pragma unroll
        for (int x = 1; x < 16; x++) {
            float v = sMin[tid][x];
            int i2 = sIdx[tid][x];
            if (v < m || (v == m && i2 < ix)) { m = v; ix = i2; }
        }
        sCode[tid] = ix;
        if (write_codes)
            out[(long)B * D_DIM + rowBase + tid] = (float)ix;
    }
    __syncthreads();

    // ---- epilogue: gather q, quantized = z + (q - z), commit partial ----
    float lsum = 0.f;
    const float4* z4 = (const float4*)z;
    const float4* e4 = (const float4*)embed;
    float4* o4 = (float4*)out;
#pragma unroll 4
    for (int i = tid; i < TM * (D_DIM / 4); i += NTHREADS) {
        int r = i >> 6;
        int c = i & 63;
        int code = sCode[r];
        float4 qv = __ldg(&e4[(long)code * (D_DIM / 4) + c]);
        float4 zv = z4[(rowBase + r) * (D_DIM / 4) + c];
        float dx = __fsub_rn(qv.x, zv.x);
        float dy = __fsub_rn(qv.y, zv.y);
        float dz = __fsub_rn(qv.z, zv.z);
        float dw = __fsub_rn(qv.w, zv.w);
        float4 ov;
        ov.x = __fadd_rn(zv.x, dx);
        ov.y = __fadd_rn(zv.y, dy);
        ov.z = __fadd_rn(zv.z, dz);
        ov.w = __fadd_rn(zv.w, dw);
        o4[(rowBase + r) * (D_DIM / 4) + c] = ov;
        lsum += dx * dx + dy * dy + dz * dz + dw * dw;
    }
    sPart[tid] = lsum;
    __syncthreads();
#pragma unroll
    for (int s = NTHREADS / 2; s > 0; s >>= 1) {
        if (tid < s) sPart[tid] += sPart[tid + s];
        __syncthreads();
    }
    if (tid == 0) g_partials[blockIdx.x] = sPart[0];
}

__global__ void k_fin(float* __restrict__ out, int nblk, long BD, long B) {
    __shared__ double sp[256];
    int tid = threadIdx.x;
    double s = 0.0;
    for (int i = tid; i < nblk; i += 256) s += (double)g_partials[i];
    sp[tid] = s;
    __syncthreads();
    for (int st = 128; st > 0; st >>= 1) {
        if (tid < st) sp[tid] += sp[tid + st];
        __syncthreads();
    }
    if (tid == 0) {
        double commit = 0.25 * sp[0] / (double)BD;
        out[BD + B] = (float)commit;
    }
}

extern "C" void kernel_launch(void* const* d_in, const int* in_sizes, int n_in,
                              void* d_out, int out_size) {
    const float* z = (const float*)d_in[0];
    const float* embed = (const float*)d_in[1];
    float* out = (float*)d_out;

    int B = in_sizes[0] / D_DIM;
    long BD = (long)B * D_DIM;
    int nblk = B / TM;
    int write_codes = ((long)out_size >= BD + B) ? 1 : 0;
    int write_commit = ((long)out_size >= BD + B + 1) ? 1 : 0;

    k_rowsq_xla<<<(K_CODES + 1) / 2, 256>>>(embed, K_CODES, /*dest=*/0);
    k_rowsq_xla<<<(B + 1) / 2, 256>>>(z, B, /*dest=*/1);
    k_main<<<nblk, NTHREADS>>>(z, embed, out, B, write_codes);
    if (write_commit)
        k_fin<<<1, 256>>>(out, nblk, BD, (long)B);
}